// round 9
// baseline (speedup 1.0000x reference)
#include <cuda_runtime.h>
#include <math_constants.h>
#include <cstdint>

#define B  4
#define N  16384
#define S  4096
#define C  256

#define SPAIRS (S / 2)          // 2048 key-pairs (64 KB smem)
#define QT     256              // threads per knn block

// Final per-query weights + indices (allocation-free rule -> device globals)
__device__ float g_w[B * N * 3];
__device__ int   g_i[B * N * 3];

// ---------------------------------------------------------------------------
// f32x2 packed helpers (fma only -- min/max are NOT packed on sm_103a)
// ---------------------------------------------------------------------------
__device__ __forceinline__ uint64_t fma2_(uint64_t a, uint64_t b, uint64_t c) {
    uint64_t d;
    asm("fma.rn.f32x2 %0, %1, %2, %3;" : "=l"(d) : "l"(a), "l"(b), "l"(c));
    return d;
}
__device__ __forceinline__ uint64_t pack2_(float lo, float hi) {
    uint64_t d;
    asm("mov.b64 %0, {%1, %2};" : "=l"(d) : "f"(lo), "f"(hi));
    return d;
}
__device__ __forceinline__ void unpack2_(uint64_t v, float& lo, float& hi) {
    asm("mov.b64 {%0, %1}, %2;" : "=f"(lo), "=f"(hi) : "l"(v));
}

// Branch-free sorted-3 insert with indices; strict < keeps earliest index on
// ties (matches jax.lax.top_k). Only used in pass 2 (rare).
#define FLAT_INSERT(d, s) do {                                   \
    const bool q0 = (d) < d0;                                    \
    const bool q1 = (d) < d1;                                    \
    const bool q2 = (d) < d2;                                    \
    const float od1 = d1; const int oi1 = i1;                    \
    const float od0 = d0; const int oi0 = i0;                    \
    d2 = q2 ? (q1 ? od1 : (d)) : d2;                             \
    i2 = q2 ? (q1 ? oi1 : (s)) : i2;                             \
    d1 = q1 ? (q0 ? od0 : (d)) : d1;                             \
    i1 = q1 ? (q0 ? oi0 : (s)) : i1;                             \
    d0 = q0 ? (d) : d0;                                          \
    i0 = q0 ? (s) : i0;                                          \
} while (0)

// Index-free scalar sorted-3 insert: 5 FMNMX, no branches
#define NET_INSERT(v) do {                                       \
    const float c0 = fmaxf(t0, (v));                             \
    t0 = fminf(t0, (v));                                         \
    const float c1 = fmaxf(t1, c0);                              \
    t1 = fminf(t1, c0);                                          \
    t2 = fminf(t2, c1);                                          \
} while (0)

// Identical distance chain in both passes (bitwise-equal recompute)
#define DIST2(Axy, Zzw) fma2_(ax2, (Axy).x, fma2_(ay2, (Axy).y, fma2_(az2, (Zzw).x, (Zzw).y)))

// ---------------------------------------------------------------------------
// Fused exact two-pass 3-NN, 1 query/thread, all 4096 keys in smem.
// Keys packed as pairs: kp[2p] = {x0,x1 | y0,y1}, kp[2p+1] = {z0,z1 | kk0,kk1}.
// d' = kk - 2 q.k  (qq dropped: top-k invariant; re-added for weights).
// Pass 1: branch-free sorted-3 of PAIR-MINS -> thr >= true 3rd-smallest
//         (pair-mins are a subset of distances, so their 3rd-smallest is a
//          safe upper bound on the true 3rd-smallest).
// Pass 2: rescan with bitwise-identical distances; exact insert for d' <= thr.
// ---------------------------------------------------------------------------
__global__ void __launch_bounds__(QT) knn_kernel(const float* __restrict__ q,
                                                 const float* __restrict__ k)
{
    extern __shared__ ulonglong2 kp[];   // SPAIRS*2 entries = 64 KB

    const int b = blockIdx.y;
    const int n = blockIdx.x * QT + threadIdx.x;

    // Cooperative key load: packed pair layout + ||k||^2
    const float* kb = k + (size_t)b * S * 3;
    for (int p = threadIdx.x; p < SPAIRS; p += QT) {
        float x0 = kb[6 * p + 0], y0 = kb[6 * p + 1], z0 = kb[6 * p + 2];
        float x1 = kb[6 * p + 3], y1 = kb[6 * p + 4], z1 = kb[6 * p + 5];
        float w0 = fmaf(x0, x0, fmaf(y0, y0, z0 * z0));
        float w1 = fmaf(x1, x1, fmaf(y1, y1, z1 * z1));
        kp[2 * p]     = make_ulonglong2(pack2_(x0, x1), pack2_(y0, y1));
        kp[2 * p + 1] = make_ulonglong2(pack2_(z0, z1), pack2_(w0, w1));
    }
    __syncthreads();

    const float* qp = q + ((size_t)b * N + n) * 3;
    const float qx = qp[0], qy = qp[1], qz = qp[2];
    const float qq = fmaf(qx, qx, fmaf(qy, qy, qz * qz));
    const uint64_t ax2 = pack2_(-2.0f * qx, -2.0f * qx);
    const uint64_t ay2 = pack2_(-2.0f * qy, -2.0f * qy);
    const uint64_t az2 = pack2_(-2.0f * qz, -2.0f * qz);

    // ---- Pass 1: branch-free threshold from pair-mins
    float t0 = CUDART_INF_F, t1 = CUDART_INF_F, t2 = CUDART_INF_F;

#pragma unroll 8
    for (int p = 0; p < SPAIRS; ++p) {
        const ulonglong2 A = kp[2 * p];       // {x-pair, y-pair}
        const ulonglong2 Z = kp[2 * p + 1];   // {z-pair, kk-pair}
        const uint64_t t = DIST2(A, Z);
        float ta, tb;
        unpack2_(t, ta, tb);
        const float dm = fminf(ta, tb);
        NET_INSERT(dm);
    }
    const float thr = t2;   // >= exact 3rd-smallest d' (safe threshold)

    // ---- Pass 2: recover exact top-3 with indices (bitwise-equal d').
    float d0 = CUDART_INF_F, d1 = CUDART_INF_F, d2 = CUDART_INF_F;
    int   i0 = 0, i1 = 0, i2 = 0;

#pragma unroll 4
    for (int p = 0; p < SPAIRS; ++p) {
        const ulonglong2 A = kp[2 * p];
        const ulonglong2 Z = kp[2 * p + 1];
        const uint64_t t = DIST2(A, Z);
        float ta, tb;
        unpack2_(t, ta, tb);
        if (fminf(ta, tb) <= thr) {       // only (near-)top-3 members enter
            // Insert in index order (2p first): FLAT_INSERT's strict <
            // preserves earliest-index-on-tie == top_k semantics.
            FLAT_INSERT(ta, 2 * p);
            FLAT_INSERT(tb, 2 * p + 1);
        }
    }

    // Weights from exact distances (d' + qq)
    const float r0 = 1.0f / (d0 + qq + 1e-8f);
    const float r1 = 1.0f / (d1 + qq + 1e-8f);
    const float r2 = 1.0f / (d2 + qq + 1e-8f);
    const float inv = 1.0f / (r0 + r1 + r2);

    const int base = (b * N + n) * 3;
    g_w[base + 0] = r0 * inv;  g_i[base + 0] = i0;
    g_w[base + 1] = r1 * inv;  g_i[base + 1] = i1;
    g_w[base + 2] = r2 * inv;  g_i[base + 2] = i2;
}

// ---------------------------------------------------------------------------
// Phase 2: weighted gather (float4 rows of v) + transpose to out[b][c][n].
// NQ=16 -> 17 KB smem -> 8 blocks/SM.
// ---------------------------------------------------------------------------
#define NQ 16

__global__ void __launch_bounds__(256) gather_kernel(const float* __restrict__ v,
                                                     float* __restrict__ out)
{
    __shared__ float buf[NQ][C + 4];   // rows 16B-aligned for STS.128
    __shared__ float w[NQ * 3];
    __shared__ int   id[NQ * 3];

    const int b   = blockIdx.y;
    const int n0  = blockIdx.x * NQ;
    const int tid = threadIdx.x;       // 256 threads

    if (tid < NQ * 3) {
        const int base = (b * N + n0) * 3;
        w[tid]  = g_w[base + tid];
        id[tid] = g_i[base + tid];
    }
    __syncthreads();

    const float4* vb4 = (const float4*)(v + (size_t)b * S * C);
    const int c4 = tid & 63;          // float4 channel slot (64 per row)
    const int qo = tid >> 6;          // 4 queries per iteration

#pragma unroll
    for (int qb = 0; qb < NQ; qb += 4) {
        const int ql = qb + qo;
        const int   j0 = id[ql * 3 + 0], j1 = id[ql * 3 + 1], j2 = id[ql * 3 + 2];
        const float w0 = w[ql * 3 + 0],  w1 = w[ql * 3 + 1],  w2 = w[ql * 3 + 2];
        const float4 a0 = vb4[j0 * 64 + c4];
        const float4 a1 = vb4[j1 * 64 + c4];
        const float4 a2 = vb4[j2 * 64 + c4];
        float4 r;
        r.x = fmaf(w0, a0.x, fmaf(w1, a1.x, w2 * a2.x));
        r.y = fmaf(w0, a0.y, fmaf(w1, a1.y, w2 * a2.y));
        r.z = fmaf(w0, a0.z, fmaf(w1, a1.z, w2 * a2.z));
        r.w = fmaf(w0, a0.w, fmaf(w1, a1.w, w2 * a2.w));
        *(float4*)&buf[ql][c4 * 4] = r;   // STS.128
    }
    __syncthreads();

    // Transposed write: each warp covers 2 channels per iter (16 n per half-warp)
    const int lane = tid & 31;
    const int warp = tid >> 5;
    const int nloc = lane & 15;
    const int csub = lane >> 4;
    float* ob = out + (size_t)b * C * N + n0;
#pragma unroll
    for (int it = 0; it < 16; ++it) {
        const int c = it * 16 + warp * 2 + csub;
        ob[c * N + nloc] = buf[nloc][c];
    }
}

// ---------------------------------------------------------------------------
extern "C" void kernel_launch(void* const* d_in, const int* in_sizes, int n_in,
                              void* d_out, int out_size)
{
    const float* q = (const float*)d_in[0];   // (B, N, 3)
    const float* k = (const float*)d_in[1];   // (B, S, 3)
    const float* v = (const float*)d_in[2];   // (B, S, C)
    float* out = (float*)d_out;               // (B, C, N)

    static_assert(SPAIRS * 2 * sizeof(ulonglong2) == 65536, "smem size");
    cudaFuncSetAttribute(knn_kernel,
                         cudaFuncAttributeMaxDynamicSharedMemorySize, 65536);

    dim3 g1(N / QT, B);                       // 64 x 4 = 256 blocks
    knn_kernel<<<g1, QT, 65536>>>(q, k);

    dim3 g2(N / NQ, B);                       // 1024 x 4 = 4096 blocks
    gather_kernel<<<g2, 256>>>(v, out);
}

// round 10
// speedup vs baseline: 1.0039x; 1.0039x over previous
#include <cuda_runtime.h>
#include <math_constants.h>
#include <cstdint>

#define B  4
#define N  16384
#define S  4096
#define C  256

#define SPAIRS (S / 2)          // 2048 key-pairs (64 KB smem)
#define QT     256              // threads per knn block

// Final per-query weights + indices (allocation-free rule -> device globals)
__device__ float g_w[B * N * 3];
__device__ int   g_i[B * N * 3];

// ---------------------------------------------------------------------------
// f32x2 packed helpers (fma only -- min/max are NOT packed on sm_103a)
// ---------------------------------------------------------------------------
__device__ __forceinline__ uint64_t fma2_(uint64_t a, uint64_t b, uint64_t c) {
    uint64_t d;
    asm("fma.rn.f32x2 %0, %1, %2, %3;" : "=l"(d) : "l"(a), "l"(b), "l"(c));
    return d;
}
__device__ __forceinline__ uint64_t pack2_(float lo, float hi) {
    uint64_t d;
    asm("mov.b64 %0, {%1, %2};" : "=l"(d) : "f"(lo), "f"(hi));
    return d;
}
__device__ __forceinline__ void unpack2_(uint64_t v, float& lo, float& hi) {
    asm("mov.b64 {%0, %1}, %2;" : "=f"(lo), "=f"(hi) : "l"(v));
}

// Branch-free sorted-3 insert with indices; strict < keeps earliest index on
// ties (matches jax.lax.top_k). Only used in pass 2 (rare).
#define FLAT_INSERT(d, s) do {                                   \
    const bool q0 = (d) < d0;                                    \
    const bool q1 = (d) < d1;                                    \
    const bool q2 = (d) < d2;                                    \
    const float od1 = d1; const int oi1 = i1;                    \
    const float od0 = d0; const int oi0 = i0;                    \
    d2 = q2 ? (q1 ? od1 : (d)) : d2;                             \
    i2 = q2 ? (q1 ? oi1 : (s)) : i2;                             \
    d1 = q1 ? (q0 ? od0 : (d)) : d1;                             \
    i1 = q1 ? (q0 ? oi0 : (s)) : i1;                             \
    d0 = q0 ? (d) : d0;                                          \
    i0 = q0 ? (s) : i0;                                          \
} while (0)

// Index-free scalar sorted-3 insert: 5 FMNMX, no branches
#define NET_INSERT(v) do {                                       \
    const float c0 = fmaxf(t0, (v));                             \
    t0 = fminf(t0, (v));                                         \
    const float c1 = fmaxf(t1, c0);                              \
    t1 = fminf(t1, c0);                                          \
    t2 = fminf(t2, c1);                                          \
} while (0)

// Identical distance chain in both passes (bitwise-equal recompute)
#define DIST2(Axy, Zzw) fma2_(ax2, (Axy).x, fma2_(ay2, (Axy).y, fma2_(az2, (Zzw).x, (Zzw).y)))

// ---------------------------------------------------------------------------
// Fused exact two-pass 3-NN, 1 query/thread, all 4096 keys in smem.
// Keys packed as pairs: kp[2p] = {x0,x1 | y0,y1}, kp[2p+1] = {z0,z1 | kk0,kk1}.
// d' = kk - 2 q.k  (qq dropped: top-k invariant; re-added for weights).
// Pass 1: branch-free sorted-3 of PAIR-MINS -> thr >= true 3rd-smallest
//         (pair-mins are a subset of distances, so their 3rd-smallest is a
//          safe upper bound on the true 3rd-smallest).
// Pass 2: rescan with bitwise-identical distances; exact insert for d' <= thr.
// ---------------------------------------------------------------------------
__global__ void __launch_bounds__(QT) knn_kernel(const float* __restrict__ q,
                                                 const float* __restrict__ k)
{
    extern __shared__ ulonglong2 kp[];   // SPAIRS*2 entries = 64 KB

    const int b = blockIdx.y;
    const int n = blockIdx.x * QT + threadIdx.x;

    // Cooperative key load: packed pair layout + ||k||^2
    const float* kb = k + (size_t)b * S * 3;
    for (int p = threadIdx.x; p < SPAIRS; p += QT) {
        float x0 = kb[6 * p + 0], y0 = kb[6 * p + 1], z0 = kb[6 * p + 2];
        float x1 = kb[6 * p + 3], y1 = kb[6 * p + 4], z1 = kb[6 * p + 5];
        float w0 = fmaf(x0, x0, fmaf(y0, y0, z0 * z0));
        float w1 = fmaf(x1, x1, fmaf(y1, y1, z1 * z1));
        kp[2 * p]     = make_ulonglong2(pack2_(x0, x1), pack2_(y0, y1));
        kp[2 * p + 1] = make_ulonglong2(pack2_(z0, z1), pack2_(w0, w1));
    }
    __syncthreads();

    const float* qp = q + ((size_t)b * N + n) * 3;
    const float qx = qp[0], qy = qp[1], qz = qp[2];
    const float qq = fmaf(qx, qx, fmaf(qy, qy, qz * qz));
    const uint64_t ax2 = pack2_(-2.0f * qx, -2.0f * qx);
    const uint64_t ay2 = pack2_(-2.0f * qy, -2.0f * qy);
    const uint64_t az2 = pack2_(-2.0f * qz, -2.0f * qz);

    // ---- Pass 1: branch-free threshold from pair-mins
    float t0 = CUDART_INF_F, t1 = CUDART_INF_F, t2 = CUDART_INF_F;

#pragma unroll 8
    for (int p = 0; p < SPAIRS; ++p) {
        const ulonglong2 A = kp[2 * p];       // {x-pair, y-pair}
        const ulonglong2 Z = kp[2 * p + 1];   // {z-pair, kk-pair}
        const uint64_t t = DIST2(A, Z);
        float ta, tb;
        unpack2_(t, ta, tb);
        const float dm = fminf(ta, tb);
        NET_INSERT(dm);
    }
    const float thr = t2;   // >= exact 3rd-smallest d' (safe threshold)

    // ---- Pass 2: recover exact top-3 with indices (bitwise-equal d').
    float d0 = CUDART_INF_F, d1 = CUDART_INF_F, d2 = CUDART_INF_F;
    int   i0 = 0, i1 = 0, i2 = 0;

#pragma unroll 4
    for (int p = 0; p < SPAIRS; ++p) {
        const ulonglong2 A = kp[2 * p];
        const ulonglong2 Z = kp[2 * p + 1];
        const uint64_t t = DIST2(A, Z);
        float ta, tb;
        unpack2_(t, ta, tb);
        if (fminf(ta, tb) <= thr) {       // only (near-)top-3 members enter
            // Insert in index order (2p first): FLAT_INSERT's strict <
            // preserves earliest-index-on-tie == top_k semantics.
            FLAT_INSERT(ta, 2 * p);
            FLAT_INSERT(tb, 2 * p + 1);
        }
    }

    // Weights from exact distances (d' + qq)
    const float r0 = 1.0f / (d0 + qq + 1e-8f);
    const float r1 = 1.0f / (d1 + qq + 1e-8f);
    const float r2 = 1.0f / (d2 + qq + 1e-8f);
    const float inv = 1.0f / (r0 + r1 + r2);

    const int base = (b * N + n) * 3;
    g_w[base + 0] = r0 * inv;  g_i[base + 0] = i0;
    g_w[base + 1] = r1 * inv;  g_i[base + 1] = i1;
    g_w[base + 2] = r2 * inv;  g_i[base + 2] = i2;
}

// ---------------------------------------------------------------------------
// Phase 2: weighted gather (float4 rows of v) + transpose to out[b][c][n].
// NQ=16 -> 17 KB smem -> 8 blocks/SM.
// ---------------------------------------------------------------------------
#define NQ 16

__global__ void __launch_bounds__(256) gather_kernel(const float* __restrict__ v,
                                                     float* __restrict__ out)
{
    __shared__ float buf[NQ][C + 4];   // rows 16B-aligned for STS.128
    __shared__ float w[NQ * 3];
    __shared__ int   id[NQ * 3];

    const int b   = blockIdx.y;
    const int n0  = blockIdx.x * NQ;
    const int tid = threadIdx.x;       // 256 threads

    if (tid < NQ * 3) {
        const int base = (b * N + n0) * 3;
        w[tid]  = g_w[base + tid];
        id[tid] = g_i[base + tid];
    }
    __syncthreads();

    const float4* vb4 = (const float4*)(v + (size_t)b * S * C);
    const int c4 = tid & 63;          // float4 channel slot (64 per row)
    const int qo = tid >> 6;          // 4 queries per iteration

#pragma unroll
    for (int qb = 0; qb < NQ; qb += 4) {
        const int ql = qb + qo;
        const int   j0 = id[ql * 3 + 0], j1 = id[ql * 3 + 1], j2 = id[ql * 3 + 2];
        const float w0 = w[ql * 3 + 0],  w1 = w[ql * 3 + 1],  w2 = w[ql * 3 + 2];
        const float4 a0 = vb4[j0 * 64 + c4];
        const float4 a1 = vb4[j1 * 64 + c4];
        const float4 a2 = vb4[j2 * 64 + c4];
        float4 r;
        r.x = fmaf(w0, a0.x, fmaf(w1, a1.x, w2 * a2.x));
        r.y = fmaf(w0, a0.y, fmaf(w1, a1.y, w2 * a2.y));
        r.z = fmaf(w0, a0.z, fmaf(w1, a1.z, w2 * a2.z));
        r.w = fmaf(w0, a0.w, fmaf(w1, a1.w, w2 * a2.w));
        *(float4*)&buf[ql][c4 * 4] = r;   // STS.128
    }
    __syncthreads();

    // Transposed write: each warp covers 2 channels per iter (16 n per half-warp)
    const int lane = tid & 31;
    const int warp = tid >> 5;
    const int nloc = lane & 15;
    const int csub = lane >> 4;
    float* ob = out + (size_t)b * C * N + n0;
#pragma unroll
    for (int it = 0; it < 16; ++it) {
        const int c = it * 16 + warp * 2 + csub;
        ob[c * N + nloc] = buf[nloc][c];
    }
}

// ---------------------------------------------------------------------------
extern "C" void kernel_launch(void* const* d_in, const int* in_sizes, int n_in,
                              void* d_out, int out_size)
{
    const float* q = (const float*)d_in[0];   // (B, N, 3)
    const float* k = (const float*)d_in[1];   // (B, S, 3)
    const float* v = (const float*)d_in[2];   // (B, S, C)
    float* out = (float*)d_out;               // (B, C, N)

    static_assert(SPAIRS * 2 * sizeof(ulonglong2) == 65536, "smem size");
    cudaFuncSetAttribute(knn_kernel,
                         cudaFuncAttributeMaxDynamicSharedMemorySize, 65536);

    dim3 g1(N / QT, B);                       // 64 x 4 = 256 blocks
    knn_kernel<<<g1, QT, 65536>>>(q, k);

    dim3 g2(N / NQ, B);                       // 1024 x 4 = 4096 blocks
    gather_kernel<<<g2, 256>>>(v, out);
}

// round 11
// speedup vs baseline: 1.0054x; 1.0015x over previous
#include <cuda_runtime.h>
#include <math_constants.h>
#include <cstdint>

#define B  4
#define N  16384
#define S  4096
#define C  256

#define SPAIRS (S / 2)          // 2048 key-pairs (64 KB smem)
#define QT     256              // threads per knn block

// Final per-query weights + indices (allocation-free rule -> device globals)
__device__ float g_w[B * N * 3];
__device__ int   g_i[B * N * 3];

// ---------------------------------------------------------------------------
// f32x2 packed helpers (fma only -- min/max are NOT packed on sm_103a)
// ---------------------------------------------------------------------------
__device__ __forceinline__ uint64_t fma2_(uint64_t a, uint64_t b, uint64_t c) {
    uint64_t d;
    asm("fma.rn.f32x2 %0, %1, %2, %3;" : "=l"(d) : "l"(a), "l"(b), "l"(c));
    return d;
}
__device__ __forceinline__ uint64_t pack2_(float lo, float hi) {
    uint64_t d;
    asm("mov.b64 %0, {%1, %2};" : "=l"(d) : "f"(lo), "f"(hi));
    return d;
}
__device__ __forceinline__ void unpack2_(uint64_t v, float& lo, float& hi) {
    asm("mov.b64 {%0, %1}, %2;" : "=f"(lo), "=f"(hi) : "l"(v));
}

// Branch-free sorted-3 insert with indices; strict < keeps earliest index on
// ties (matches jax.lax.top_k). Only used in pass 2 (rare).
#define FLAT_INSERT(d, s) do {                                   \
    const bool q0 = (d) < d0;                                    \
    const bool q1 = (d) < d1;                                    \
    const bool q2 = (d) < d2;                                    \
    const float od1 = d1; const int oi1 = i1;                    \
    const float od0 = d0; const int oi0 = i0;                    \
    d2 = q2 ? (q1 ? od1 : (d)) : d2;                             \
    i2 = q2 ? (q1 ? oi1 : (s)) : i2;                             \
    d1 = q1 ? (q0 ? od0 : (d)) : d1;                             \
    i1 = q1 ? (q0 ? oi0 : (s)) : i1;                             \
    d0 = q0 ? (d) : d0;                                          \
    i0 = q0 ? (s) : i0;                                          \
} while (0)

// Index-free scalar sorted-3 insert: 5 FMNMX, no branches
#define NET_INSERT(v) do {                                       \
    const float c0 = fmaxf(t0, (v));                             \
    t0 = fminf(t0, (v));                                         \
    const float c1 = fmaxf(t1, c0);                              \
    t1 = fminf(t1, c0);                                          \
    t2 = fminf(t2, c1);                                          \
} while (0)

// Identical distance chain in both passes (bitwise-equal recompute)
#define DIST2(Axy, Zzw) fma2_(ax2, (Axy).x, fma2_(ay2, (Axy).y, fma2_(az2, (Zzw).x, (Zzw).y)))

// ---------------------------------------------------------------------------
// Fused exact two-pass 3-NN, 1 query/thread, all 4096 keys in smem.
// Keys packed as pairs: kp[2p] = {x0,x1 | y0,y1}, kp[2p+1] = {z0,z1 | kk0,kk1}.
// d' = kk - 2 q.k  (qq dropped: top-k invariant; re-added for weights).
// Pass 1: branch-free sorted-3 of PAIR-MINS -> thr >= true 3rd-smallest
//         (pair-mins are a subset of distances, so their 3rd-smallest is a
//          safe upper bound on the true 3rd-smallest).
// Pass 2: rescan with bitwise-identical distances; exact insert for d' <= thr.
// ---------------------------------------------------------------------------
__global__ void __launch_bounds__(QT) knn_kernel(const float* __restrict__ q,
                                                 const float* __restrict__ k)
{
    extern __shared__ ulonglong2 kp[];   // SPAIRS*2 entries = 64 KB

    const int b = blockIdx.y;
    const int n = blockIdx.x * QT + threadIdx.x;

    // Cooperative key load: packed pair layout + ||k||^2
    const float* kb = k + (size_t)b * S * 3;
    for (int p = threadIdx.x; p < SPAIRS; p += QT) {
        float x0 = kb[6 * p + 0], y0 = kb[6 * p + 1], z0 = kb[6 * p + 2];
        float x1 = kb[6 * p + 3], y1 = kb[6 * p + 4], z1 = kb[6 * p + 5];
        float w0 = fmaf(x0, x0, fmaf(y0, y0, z0 * z0));
        float w1 = fmaf(x1, x1, fmaf(y1, y1, z1 * z1));
        kp[2 * p]     = make_ulonglong2(pack2_(x0, x1), pack2_(y0, y1));
        kp[2 * p + 1] = make_ulonglong2(pack2_(z0, z1), pack2_(w0, w1));
    }
    __syncthreads();

    const float* qp = q + ((size_t)b * N + n) * 3;
    const float qx = qp[0], qy = qp[1], qz = qp[2];
    const float qq = fmaf(qx, qx, fmaf(qy, qy, qz * qz));
    const uint64_t ax2 = pack2_(-2.0f * qx, -2.0f * qx);
    const uint64_t ay2 = pack2_(-2.0f * qy, -2.0f * qy);
    const uint64_t az2 = pack2_(-2.0f * qz, -2.0f * qz);

    // ---- Pass 1: branch-free threshold from pair-mins
    float t0 = CUDART_INF_F, t1 = CUDART_INF_F, t2 = CUDART_INF_F;

#pragma unroll 8
    for (int p = 0; p < SPAIRS; ++p) {
        const ulonglong2 A = kp[2 * p];       // {x-pair, y-pair}
        const ulonglong2 Z = kp[2 * p + 1];   // {z-pair, kk-pair}
        const uint64_t t = DIST2(A, Z);
        float ta, tb;
        unpack2_(t, ta, tb);
        const float dm = fminf(ta, tb);
        NET_INSERT(dm);
    }
    const float thr = t2;   // >= exact 3rd-smallest d' (safe threshold)

    // ---- Pass 2: recover exact top-3 with indices (bitwise-equal d').
    float d0 = CUDART_INF_F, d1 = CUDART_INF_F, d2 = CUDART_INF_F;
    int   i0 = 0, i1 = 0, i2 = 0;

#pragma unroll 4
    for (int p = 0; p < SPAIRS; ++p) {
        const ulonglong2 A = kp[2 * p];
        const ulonglong2 Z = kp[2 * p + 1];
        const uint64_t t = DIST2(A, Z);
        float ta, tb;
        unpack2_(t, ta, tb);
        if (fminf(ta, tb) <= thr) {       // only (near-)top-3 members enter
            // Insert in index order (2p first): FLAT_INSERT's strict <
            // preserves earliest-index-on-tie == top_k semantics.
            FLAT_INSERT(ta, 2 * p);
            FLAT_INSERT(tb, 2 * p + 1);
        }
    }

    // Weights from exact distances (d' + qq)
    const float r0 = 1.0f / (d0 + qq + 1e-8f);
    const float r1 = 1.0f / (d1 + qq + 1e-8f);
    const float r2 = 1.0f / (d2 + qq + 1e-8f);
    const float inv = 1.0f / (r0 + r1 + r2);

    const int base = (b * N + n) * 3;
    g_w[base + 0] = r0 * inv;  g_i[base + 0] = i0;
    g_w[base + 1] = r1 * inv;  g_i[base + 1] = i1;
    g_w[base + 2] = r2 * inv;  g_i[base + 2] = i2;
}

// ---------------------------------------------------------------------------
// Phase 2: weighted gather (float4 rows of v) + transpose to out[b][c][n].
// NQ=16 -> 17 KB smem -> 8 blocks/SM.
// ---------------------------------------------------------------------------
#define NQ 16

__global__ void __launch_bounds__(256) gather_kernel(const float* __restrict__ v,
                                                     float* __restrict__ out)
{
    __shared__ float buf[NQ][C + 4];   // rows 16B-aligned for STS.128
    __shared__ float w[NQ * 3];
    __shared__ int   id[NQ * 3];

    const int b   = blockIdx.y;
    const int n0  = blockIdx.x * NQ;
    const int tid = threadIdx.x;       // 256 threads

    if (tid < NQ * 3) {
        const int base = (b * N + n0) * 3;
        w[tid]  = g_w[base + tid];
        id[tid] = g_i[base + tid];
    }
    __syncthreads();

    const float4* vb4 = (const float4*)(v + (size_t)b * S * C);
    const int c4 = tid & 63;          // float4 channel slot (64 per row)
    const int qo = tid >> 6;          // 4 queries per iteration

#pragma unroll
    for (int qb = 0; qb < NQ; qb += 4) {
        const int ql = qb + qo;
        const int   j0 = id[ql * 3 + 0], j1 = id[ql * 3 + 1], j2 = id[ql * 3 + 2];
        const float w0 = w[ql * 3 + 0],  w1 = w[ql * 3 + 1],  w2 = w[ql * 3 + 2];
        const float4 a0 = vb4[j0 * 64 + c4];
        const float4 a1 = vb4[j1 * 64 + c4];
        const float4 a2 = vb4[j2 * 64 + c4];
        float4 r;
        r.x = fmaf(w0, a0.x, fmaf(w1, a1.x, w2 * a2.x));
        r.y = fmaf(w0, a0.y, fmaf(w1, a1.y, w2 * a2.y));
        r.z = fmaf(w0, a0.z, fmaf(w1, a1.z, w2 * a2.z));
        r.w = fmaf(w0, a0.w, fmaf(w1, a1.w, w2 * a2.w));
        *(float4*)&buf[ql][c4 * 4] = r;   // STS.128
    }
    __syncthreads();

    // Transposed write: each warp covers 2 channels per iter (16 n per half-warp)
    const int lane = tid & 31;
    const int warp = tid >> 5;
    const int nloc = lane & 15;
    const int csub = lane >> 4;
    float* ob = out + (size_t)b * C * N + n0;
#pragma unroll
    for (int it = 0; it < 16; ++it) {
        const int c = it * 16 + warp * 2 + csub;
        ob[c * N + nloc] = buf[nloc][c];
    }
}

// ---------------------------------------------------------------------------
extern "C" void kernel_launch(void* const* d_in, const int* in_sizes, int n_in,
                              void* d_out, int out_size)
{
    const float* q = (const float*)d_in[0];   // (B, N, 3)
    const float* k = (const float*)d_in[1];   // (B, S, 3)
    const float* v = (const float*)d_in[2];   // (B, S, C)
    float* out = (float*)d_out;               // (B, C, N)

    static_assert(SPAIRS * 2 * sizeof(ulonglong2) == 65536, "smem size");
    cudaFuncSetAttribute(knn_kernel,
                         cudaFuncAttributeMaxDynamicSharedMemorySize, 65536);

    dim3 g1(N / QT, B);                       // 64 x 4 = 256 blocks
    knn_kernel<<<g1, QT, 65536>>>(q, k);

    dim3 g2(N / NQ, B);                       // 1024 x 4 = 4096 blocks
    gather_kernel<<<g2, 256>>>(v, out);
}